// round 1
// baseline (speedup 1.0000x reference)
#include <cuda_runtime.h>
#include <math.h>

#define DEV_INLINE __device__ __forceinline__

// Problem constants
#define kB    4
#define kL    4096
#define kD    1024
#define kHID  128
#define kNS   1024
#define kNTOK (kB * kL)          // 16384

// GEMM tiling
#define BM 64
#define BN 256
#define BK 32

// Scan partitioning
#define kNSEQ  (kB * kNS)        // 4096 sequences
#define kCH    64                // chunks per sequence
#define kT     64                // timesteps per chunk

#define SMEM_FLOATS (BK*BM + BK*BN + BM*BN + kNS)

// Scratch (static device globals — no allocation)
__device__ float g_u[(size_t)kNTOK * kNS];     // 64 MB: u = K * nu
__device__ float g_Ag[kNSEQ * kCH];
__device__ float g_Vg[kNSEQ * kCH];
__device__ float g_cr[kNSEQ * kCH];

DEV_INLINE unsigned long long pack2(float lo, float hi) {
    unsigned long long r;
    asm("mov.b64 %0, {%1, %2};" : "=l"(r) : "f"(lo), "f"(hi));
    return r;
}
DEV_INLINE void unpack2(unsigned long long v, float& lo, float& hi) {
    asm("mov.b64 {%0, %1}, %2;" : "=f"(lo), "=f"(hi) : "l"(v));
}
// Packed fp32x2 FMA — full-rate fp32 path on sm_103a (ptxas never emits it from C++)
DEV_INLINE void fma2(unsigned long long& d, unsigned long long a, unsigned long long b) {
    asm("fma.rn.f32x2 %0, %1, %2, %0;" : "+l"(d) : "l"(a), "l"(b));
}

DEV_INLINE float gelu_exact(float v) {
    return 0.5f * v * (1.0f + erff(v * 0.70710678118654752440f));
}

// ---------------------------------------------------------------------------
// Fused kernel: per 64-token block
//   Phase 1: H[64,256] = gelu(X @ [Wr1|Wm1] + [br1|bm1])    (K = 1024)
//   Phase 2: for each 256-wide channel slice:
//              z  = pi*tanh(Hm @ Wm2 + bm2)   (kept in registers)
//              lR = clip(Hr @ Wr2 + br2)
//              R = exp(lR); K = Pi/max(Pi+R,1e-8); nu = wrap(z - theta); u = K*nu
//            writes R, K to d_out and u to scratch.
// ---------------------------------------------------------------------------
__global__ __launch_bounds__(256, 1)
void mlp_fused_kernel(const float* __restrict__ theta,
                      const float* __restrict__ x,
                      const float* __restrict__ logPi,
                      const float* __restrict__ Wr1, const float* __restrict__ br1,
                      const float* __restrict__ Wr2, const float* __restrict__ br2,
                      const float* __restrict__ Wm1, const float* __restrict__ bm1,
                      const float* __restrict__ Wm2, const float* __restrict__ bm2,
                      float* __restrict__ outK, float* __restrict__ outR)
{
    extern __shared__ float sm[];
    float* As  = sm;                   // [BK][BM]  X tile (k-major)
    float* Ws  = As + BK*BM;           // [BK][BN]  weight tile
    float* Hb  = Ws + BK*BN;           // [BM][BN]  hidden activations (token-major)
    float* PiB = Hb + BM*BN;           // [kNS]     exp(log_Pi)

    const int tid = threadIdx.x;
    const int tx  = tid & 31;          // 0..31 -> 8-col micro-tile (4 + 4 split)
    const int ty  = tid >> 5;          // 0..7  -> 8-row micro-tile (4 + 4 split)
    const int tok0 = blockIdx.x * BM;

    for (int i = tid; i < kNS; i += 256) PiB[i] = expf(logPi[i]);

    unsigned long long acc[8][4];
#pragma unroll
    for (int i = 0; i < 8; ++i)
#pragma unroll
        for (int j = 0; j < 4; ++j) acc[i][j] = 0ULL;

    // ---------------- Phase 1 ----------------
    for (int k0 = 0; k0 < kD; k0 += BK) {
        __syncthreads();
        // X tile -> As (transposed)
#pragma unroll
        for (int r = 0; r < 2; ++r) {
            int f = tid * 2 + r;             // float4 index
            int m = f >> 3, k4 = f & 7;
            float4 v = *(const float4*)&x[(size_t)(tok0 + m) * kD + k0 + k4 * 4];
            As[(k4*4+0)*BM + m] = v.x;
            As[(k4*4+1)*BM + m] = v.y;
            As[(k4*4+2)*BM + m] = v.z;
            As[(k4*4+3)*BM + m] = v.w;
        }
        // [Wr1 | Wm1] tile -> Ws
#pragma unroll
        for (int r = 0; r < 8; ++r) {
            int f = tid + r * 256;
            int k = f >> 6, n4 = f & 63;
            const float* src = (n4 < 32)
                ? (Wr1 + (size_t)(k0 + k) * kHID + n4 * 4)
                : (Wm1 + (size_t)(k0 + k) * kHID + (n4 - 32) * 4);
            *(float4*)&Ws[k*BN + n4*4] = *(const float4*)src;
        }
        __syncthreads();
#pragma unroll 8
        for (int kk = 0; kk < BK; ++kk) {
            float4 a0 = *(const float4*)&As[kk*BM + ty*4];
            float4 a1 = *(const float4*)&As[kk*BM + 32 + ty*4];
            float4 b0 = *(const float4*)&Ws[kk*BN + tx*4];
            float4 b1 = *(const float4*)&Ws[kk*BN + 128 + tx*4];
            unsigned long long pb0 = pack2(b0.x, b0.y), pb1 = pack2(b0.z, b0.w);
            unsigned long long pb2 = pack2(b1.x, b1.y), pb3 = pack2(b1.z, b1.w);
            float av[8] = {a0.x, a0.y, a0.z, a0.w, a1.x, a1.y, a1.z, a1.w};
#pragma unroll
            for (int i = 0; i < 8; ++i) {
                unsigned long long pa = pack2(av[i], av[i]);
                fma2(acc[i][0], pa, pb0);
                fma2(acc[i][1], pa, pb1);
                fma2(acc[i][2], pa, pb2);
                fma2(acc[i][3], pa, pb3);
            }
        }
    }

    // bias + exact GELU, stash H in smem (token-major)
#pragma unroll
    for (int i = 0; i < 8; ++i) {
        int m = (i < 4) ? (ty*4 + i) : (32 + ty*4 + i - 4);
#pragma unroll
        for (int h = 0; h < 2; ++h) {
            float v0, v1, v2, v3;
            unpack2(acc[i][2*h],   v0, v1);
            unpack2(acc[i][2*h+1], v2, v3);
            const float* bptr = h ? bm1 : br1;
            int n0 = tx * 4;
            v0 = gelu_exact(v0 + bptr[n0+0]);
            v1 = gelu_exact(v1 + bptr[n0+1]);
            v2 = gelu_exact(v2 + bptr[n0+2]);
            v3 = gelu_exact(v3 + bptr[n0+3]);
            *(float4*)&Hb[m*BN + h*128 + n0] = make_float4(v0, v1, v2, v3);
        }
    }

    // ---------------- Phase 2 ----------------
    const float PIF = 3.14159265358979323846f;
    float z[8][8];

    for (int s = 0; s < 4; ++s) {                    // channel slices of 256
        for (int pass = 0; pass < 2; ++pass) {       // 0: measure head (z), 1: log_R head
            const float* W2  = pass ? Wr2 : Wm2;
            const int hbase  = pass ? 0 : 128;
#pragma unroll
            for (int i = 0; i < 8; ++i)
#pragma unroll
                for (int j = 0; j < 4; ++j) acc[i][j] = 0ULL;

            for (int k0 = 0; k0 < kHID; k0 += BK) {
                __syncthreads();
#pragma unroll
                for (int r = 0; r < 8; ++r) {
                    int f = tid + r * 256;
                    int k = f >> 6, n4 = f & 63;
                    *(float4*)&Ws[k*BN + n4*4] =
                        *(const float4*)&W2[(size_t)(k0 + k) * kNS + s*256 + n4*4];
                }
                __syncthreads();
#pragma unroll 8
                for (int kk = 0; kk < BK; ++kk) {
                    int kh = hbase + k0 + kk;
                    float av[8];
#pragma unroll
                    for (int i = 0; i < 8; ++i) {
                        int m = (i < 4) ? (ty*4 + i) : (32 + ty*4 + i - 4);
                        av[i] = Hb[m*BN + kh];       // warp-broadcast
                    }
                    float4 b0 = *(const float4*)&Ws[kk*BN + tx*4];
                    float4 b1 = *(const float4*)&Ws[kk*BN + 128 + tx*4];
                    unsigned long long pb0 = pack2(b0.x, b0.y), pb1 = pack2(b0.z, b0.w);
                    unsigned long long pb2 = pack2(b1.x, b1.y), pb3 = pack2(b1.z, b1.w);
#pragma unroll
                    for (int i = 0; i < 8; ++i) {
                        unsigned long long pa = pack2(av[i], av[i]);
                        fma2(acc[i][0], pa, pb0);
                        fma2(acc[i][1], pa, pb1);
                        fma2(acc[i][2], pa, pb2);
                        fma2(acc[i][3], pa, pb3);
                    }
                }
            }

            if (pass == 0) {
#pragma unroll
                for (int i = 0; i < 8; ++i)
#pragma unroll
                    for (int h = 0; h < 2; ++h) {
                        float v0, v1, v2, v3;
                        unpack2(acc[i][2*h],   v0, v1);
                        unpack2(acc[i][2*h+1], v2, v3);
                        int c0 = s*256 + h*128 + tx*4;
                        z[i][h*4+0] = PIF * tanhf(v0 + bm2[c0+0]);
                        z[i][h*4+1] = PIF * tanhf(v1 + bm2[c0+1]);
                        z[i][h*4+2] = PIF * tanhf(v2 + bm2[c0+2]);
                        z[i][h*4+3] = PIF * tanhf(v3 + bm2[c0+3]);
                    }
            } else {
#pragma unroll
                for (int i = 0; i < 8; ++i) {
                    int m = (i < 4) ? (ty*4 + i) : (32 + ty*4 + i - 4);
#pragma unroll
                    for (int h = 0; h < 2; ++h) {
                        float v[4];
                        unpack2(acc[i][2*h],   v[0], v[1]);
                        unpack2(acc[i][2*h+1], v[2], v[3]);
                        int c0 = s*256 + h*128 + tx*4;
                        size_t base = (size_t)(tok0 + m) * kNS + c0;
                        float4 th = *(const float4*)&theta[base];
                        float thv[4] = {th.x, th.y, th.z, th.w};
                        float Ra[4], Ka[4], Ua[4];
#pragma unroll
                        for (int q = 0; q < 4; ++q) {
                            float lr = v[q] + br2[c0+q];
                            lr = fminf(fmaxf(lr, -5.0f), 5.0f);
                            float R  = expf(lr);
                            float Pi = PiB[c0+q];
                            float K  = Pi / fmaxf(Pi + R, 1e-8f);
                            float dz = z[i][h*4+q] - thv[q];
                            float nu = atan2f(sinf(dz), cosf(dz));
                            Ra[q] = R; Ka[q] = K; Ua[q] = K * nu;
                        }
                        *(float4*)&outR[base] = make_float4(Ra[0], Ra[1], Ra[2], Ra[3]);
                        *(float4*)&outK[base] = make_float4(Ka[0], Ka[1], Ka[2], Ka[3]);
                        *(float4*)&g_u[base]  = make_float4(Ua[0], Ua[1], Ua[2], Ua[3]);
                    }
                }
            }
        }
    }
}

// ---------------------------------------------------------------------------
// Scan: d[t] = alpha[t]*d[t-1] + u[t], alpha = 1-K. Chunked 3-phase scan.
// ---------------------------------------------------------------------------
__global__ void scan_chunks_kernel(const float* __restrict__ Kp) {
    int g = blockIdx.x * blockDim.x + threadIdx.x;   // < kNSEQ*kCH = 262144
    int c = g & (kNS - 1);
    int q = g >> 10;
    int b = q & (kB - 1);
    int chunk = q >> 2;
    size_t base = ((size_t)b * kL + (size_t)chunk * kT) * kNS + c;
    float a = 1.0f, v = 0.0f;
#pragma unroll 4
    for (int t = 0; t < kT; ++t) {
        float K  = Kp[base];
        float u  = g_u[base];
        float al = 1.0f - K;
        v = fmaf(al, v, u);
        a *= al;
        base += kNS;
    }
    int seq = b * kNS + c;
    g_Ag[chunk * kNSEQ + seq] = a;
    g_Vg[chunk * kNSEQ + seq] = v;
}

__global__ void scan_agg_kernel() {
    int seq = blockIdx.x * blockDim.x + threadIdx.x;  // < 4096
    float carry = 0.0f;
    for (int j = 0; j < kCH; ++j) {
        g_cr[j * kNSEQ + seq] = carry;                // exclusive prefix
        carry = fmaf(g_Ag[j * kNSEQ + seq], carry, g_Vg[j * kNSEQ + seq]);
    }
}

__global__ void scan_apply_kernel(const float* __restrict__ Kp,
                                  const float* __restrict__ theta,
                                  float* __restrict__ outTheta) {
    int g = blockIdx.x * blockDim.x + threadIdx.x;
    int c = g & (kNS - 1);
    int q = g >> 10;
    int b = q & (kB - 1);
    int chunk = q >> 2;
    int seq = b * kNS + c;
    float d = g_cr[chunk * kNSEQ + seq];
    size_t base = ((size_t)b * kL + (size_t)chunk * kT) * kNS + c;
#pragma unroll 4
    for (int t = 0; t < kT; ++t) {
        float K = Kp[base];
        float u = g_u[base];
        d = fmaf(1.0f - K, d, u);
        outTheta[base] = theta[base] + d;
        base += kNS;
    }
}

__global__ void pi_kernel(const float* __restrict__ logPi, float* __restrict__ outPi) {
    int i = blockIdx.x * blockDim.x + threadIdx.x;
    if (i < kNS) outPi[i] = expf(logPi[i]);
}

// ---------------------------------------------------------------------------
extern "C" void kernel_launch(void* const* d_in, const int* in_sizes, int n_in,
                              void* d_out, int out_size) {
    const float* theta = (const float*)d_in[0];
    const float* x     = (const float*)d_in[1];
    const float* logPi = (const float*)d_in[2];
    const float* Wr1   = (const float*)d_in[3];
    const float* br1   = (const float*)d_in[4];
    const float* Wr2   = (const float*)d_in[5];
    const float* br2   = (const float*)d_in[6];
    const float* Wm1   = (const float*)d_in[7];
    const float* bm1   = (const float*)d_in[8];
    const float* Wm2   = (const float*)d_in[9];
    const float* bm2   = (const float*)d_in[10];

    float* out      = (float*)d_out;
    float* outTheta = out;                                  // (B,L,H,NB)
    float* outPi    = outTheta + (size_t)kNTOK * kNS;       // (H,NB)
    float* outK     = outPi + kNS;                          // (B,L,H,NB)
    float* outR     = outK + (size_t)kNTOK * kNS;           // (B,L,H,NB)

    const int smem = SMEM_FLOATS * (int)sizeof(float);      // ~108 KB
    cudaFuncSetAttribute(mlp_fused_kernel,
                         cudaFuncAttributeMaxDynamicSharedMemorySize, smem);

    mlp_fused_kernel<<<kNTOK / BM, 256, smem>>>(theta, x, logPi,
                                                Wr1, br1, Wr2, br2,
                                                Wm1, bm1, Wm2, bm2,
                                                outK, outR);
    pi_kernel<<<4, 256>>>(logPi, outPi);
    scan_chunks_kernel<<<(kNSEQ * kCH) / 256, 256>>>(outK);
    scan_agg_kernel<<<kNSEQ / 256, 256>>>();
    scan_apply_kernel<<<(kNSEQ * kCH) / 256, 256>>>(outK, theta, outTheta);
}

// round 2
// speedup vs baseline: 1.0428x; 1.0428x over previous
#include <cuda_runtime.h>
#include <math.h>

#define DEV_INLINE __device__ __forceinline__

// Problem constants
#define kB    4
#define kL    4096
#define kD    1024
#define kHID  128
#define kNS   1024
#define kNTOK (kB * kL)          // 16384

// GEMM tiling
#define BM 64
#define BN 256
#define BK 32

// Scan partitioning
#define kNSEQ  (kB * kNS)        // 4096 sequences
#define kCH    64                // chunks per sequence
#define kT     64                // timesteps per chunk

#define SMEM_FLOATS (BK*BM + BK*BN + BM*BN + kNS)

// Scratch (static device globals — no allocation)
__device__ float g_u[(size_t)kNTOK * kNS];     // 64 MB: u = K * nu
__device__ float g_Ag[kNSEQ * kCH];
__device__ float g_Vg[kNSEQ * kCH];
__device__ float g_cr[kNSEQ * kCH];

DEV_INLINE unsigned long long pack2(float lo, float hi) {
    unsigned long long r;
    asm("mov.b64 %0, {%1, %2};" : "=l"(r) : "f"(lo), "f"(hi));
    return r;
}
DEV_INLINE void unpack2(unsigned long long v, float& lo, float& hi) {
    asm("mov.b64 {%0, %1}, %2;" : "=f"(lo), "=f"(hi) : "l"(v));
}
// Packed fp32x2 FMA — full-rate fp32 path on sm_103a (ptxas never emits it from C++)
DEV_INLINE void fma2(unsigned long long& d, unsigned long long a, unsigned long long b) {
    asm("fma.rn.f32x2 %0, %1, %2, %0;" : "+l"(d) : "l"(a), "l"(b));
}

DEV_INLINE float gelu_exact(float v) {
    return 0.5f * v * (1.0f + erff(v * 0.70710678118654752440f));
}

// ---------------------------------------------------------------------------
// Fused kernel: per 64-token block
//   Phase 1: H[64,256] = gelu(X @ [Wr1|Wm1] + [br1|bm1])    (K = 1024)
//   Phase 2: for each 256-wide channel slice:
//              z  = pi*tanh(Hm @ Wm2 + bm2)   (kept in registers)
//              lR = clip(Hr @ Wr2 + br2)
//              R = exp(lR); K = Pi/max(Pi+R,1e-8); nu = wrap(z - theta); u = K*nu
//            writes R, K to d_out and u to scratch.
// ---------------------------------------------------------------------------
__global__ __launch_bounds__(256, 1)
void mlp_fused_kernel(const float* __restrict__ theta,
                      const float* __restrict__ x,
                      const float* __restrict__ logPi,
                      const float* __restrict__ Wr1, const float* __restrict__ br1,
                      const float* __restrict__ Wr2, const float* __restrict__ br2,
                      const float* __restrict__ Wm1, const float* __restrict__ bm1,
                      const float* __restrict__ Wm2, const float* __restrict__ bm2,
                      float* __restrict__ outK, float* __restrict__ outR)
{
    extern __shared__ float sm[];
    float* As  = sm;                   // [BK][BM]  X tile (k-major)
    float* Ws  = As + BK*BM;           // [BK][BN]  weight tile
    float* Hb  = Ws + BK*BN;           // [BM][BN]  hidden activations (token-major)
    float* PiB = Hb + BM*BN;           // [kNS]     exp(log_Pi)

    const int tid = threadIdx.x;
    const int tx  = tid & 31;          // 0..31 -> 8-col micro-tile (4 + 4 split)
    const int ty  = tid >> 5;          // 0..7  -> 8-row micro-tile (4 + 4 split)
    const int tok0 = blockIdx.x * BM;

    for (int i = tid; i < kNS; i += 256) PiB[i] = expf(logPi[i]);

    unsigned long long acc[8][4];
#pragma unroll
    for (int i = 0; i < 8; ++i)
#pragma unroll
        for (int j = 0; j < 4; ++j) acc[i][j] = 0ULL;

    // ---------------- Phase 1 ----------------
    for (int k0 = 0; k0 < kD; k0 += BK) {
        __syncthreads();
        // X tile -> As (transposed)
#pragma unroll
        for (int r = 0; r < 2; ++r) {
            int f = tid * 2 + r;             // float4 index
            int m = f >> 3, k4 = f & 7;
            float4 v = *(const float4*)&x[(size_t)(tok0 + m) * kD + k0 + k4 * 4];
            As[(k4*4+0)*BM + m] = v.x;
            As[(k4*4+1)*BM + m] = v.y;
            As[(k4*4+2)*BM + m] = v.z;
            As[(k4*4+3)*BM + m] = v.w;
        }
        // [Wr1 | Wm1] tile -> Ws
#pragma unroll
        for (int r = 0; r < 8; ++r) {
            int f = tid + r * 256;
            int k = f >> 6, n4 = f & 63;
            const float* src = (n4 < 32)
                ? (Wr1 + (size_t)(k0 + k) * kHID + n4 * 4)
                : (Wm1 + (size_t)(k0 + k) * kHID + (n4 - 32) * 4);
            *(float4*)&Ws[k*BN + n4*4] = *(const float4*)src;
        }
        __syncthreads();
#pragma unroll 8
        for (int kk = 0; kk < BK; ++kk) {
            float4 a0 = *(const float4*)&As[kk*BM + ty*4];
            float4 a1 = *(const float4*)&As[kk*BM + 32 + ty*4];
            float4 b0 = *(const float4*)&Ws[kk*BN + tx*4];
            float4 b1 = *(const float4*)&Ws[kk*BN + 128 + tx*4];
            unsigned long long pb0 = pack2(b0.x, b0.y), pb1 = pack2(b0.z, b0.w);
            unsigned long long pb2 = pack2(b1.x, b1.y), pb3 = pack2(b1.z, b1.w);
            float av[8] = {a0.x, a0.y, a0.z, a0.w, a1.x, a1.y, a1.z, a1.w};
#pragma unroll
            for (int i = 0; i < 8; ++i) {
                unsigned long long pa = pack2(av[i], av[i]);
                fma2(acc[i][0], pa, pb0);
                fma2(acc[i][1], pa, pb1);
                fma2(acc[i][2], pa, pb2);
                fma2(acc[i][3], pa, pb3);
            }
        }
    }

    // bias + exact GELU, stash H in smem (token-major)
#pragma unroll
    for (int i = 0; i < 8; ++i) {
        int m = (i < 4) ? (ty*4 + i) : (32 + ty*4 + i - 4);
#pragma unroll
        for (int h = 0; h < 2; ++h) {
            float v0, v1, v2, v3;
            unpack2(acc[i][2*h],   v0, v1);
            unpack2(acc[i][2*h+1], v2, v3);
            const float* bptr = h ? bm1 : br1;
            int n0 = tx * 4;
            v0 = gelu_exact(v0 + bptr[n0+0]);
            v1 = gelu_exact(v1 + bptr[n0+1]);
            v2 = gelu_exact(v2 + bptr[n0+2]);
            v3 = gelu_exact(v3 + bptr[n0+3]);
            *(float4*)&Hb[m*BN + h*128 + n0] = make_float4(v0, v1, v2, v3);
        }
    }

    // ---------------- Phase 2 ----------------
    const float PIF = 3.14159265358979323846f;
    float z[8][8];

    for (int s = 0; s < 4; ++s) {                    // channel slices of 256
        for (int pass = 0; pass < 2; ++pass) {       // 0: measure head (z), 1: log_R head
            const float* W2  = pass ? Wr2 : Wm2;
            const int hbase  = pass ? 0 : 128;
#pragma unroll
            for (int i = 0; i < 8; ++i)
#pragma unroll
                for (int j = 0; j < 4; ++j) acc[i][j] = 0ULL;

            for (int k0 = 0; k0 < kHID; k0 += BK) {
                __syncthreads();
#pragma unroll
                for (int r = 0; r < 8; ++r) {
                    int f = tid + r * 256;
                    int k = f >> 6, n4 = f & 63;
                    *(float4*)&Ws[k*BN + n4*4] =
                        *(const float4*)&W2[(size_t)(k0 + k) * kNS + s*256 + n4*4];
                }
                __syncthreads();
#pragma unroll 8
                for (int kk = 0; kk < BK; ++kk) {
                    int kh = hbase + k0 + kk;
                    float av[8];
#pragma unroll
                    for (int i = 0; i < 8; ++i) {
                        int m = (i < 4) ? (ty*4 + i) : (32 + ty*4 + i - 4);
                        av[i] = Hb[m*BN + kh];       // warp-broadcast
                    }
                    float4 b0 = *(const float4*)&Ws[kk*BN + tx*4];
                    float4 b1 = *(const float4*)&Ws[kk*BN + 128 + tx*4];
                    unsigned long long pb0 = pack2(b0.x, b0.y), pb1 = pack2(b0.z, b0.w);
                    unsigned long long pb2 = pack2(b1.x, b1.y), pb3 = pack2(b1.z, b1.w);
#pragma unroll
                    for (int i = 0; i < 8; ++i) {
                        unsigned long long pa = pack2(av[i], av[i]);
                        fma2(acc[i][0], pa, pb0);
                        fma2(acc[i][1], pa, pb1);
                        fma2(acc[i][2], pa, pb2);
                        fma2(acc[i][3], pa, pb3);
                    }
                }
            }

            if (pass == 0) {
#pragma unroll
                for (int i = 0; i < 8; ++i)
#pragma unroll
                    for (int h = 0; h < 2; ++h) {
                        float v0, v1, v2, v3;
                        unpack2(acc[i][2*h],   v0, v1);
                        unpack2(acc[i][2*h+1], v2, v3);
                        int c0 = s*256 + h*128 + tx*4;
                        z[i][h*4+0] = PIF * tanhf(v0 + bm2[c0+0]);
                        z[i][h*4+1] = PIF * tanhf(v1 + bm2[c0+1]);
                        z[i][h*4+2] = PIF * tanhf(v2 + bm2[c0+2]);
                        z[i][h*4+3] = PIF * tanhf(v3 + bm2[c0+3]);
                    }
            } else {
#pragma unroll
                for (int i = 0; i < 8; ++i) {
                    int m = (i < 4) ? (ty*4 + i) : (32 + ty*4 + i - 4);
#pragma unroll
                    for (int h = 0; h < 2; ++h) {
                        float v[4];
                        unpack2(acc[i][2*h],   v[0], v[1]);
                        unpack2(acc[i][2*h+1], v[2], v[3]);
                        int c0 = s*256 + h*128 + tx*4;
                        size_t base = (size_t)(tok0 + m) * kNS + c0;
                        float4 th = *(const float4*)&theta[base];
                        float thv[4] = {th.x, th.y, th.z, th.w};
                        float Ra[4], Ka[4], Ua[4];
#pragma unroll
                        for (int q = 0; q < 4; ++q) {
                            float lr = v[q] + br2[c0+q];
                            lr = fminf(fmaxf(lr, -5.0f), 5.0f);
                            float R  = expf(lr);
                            float Pi = PiB[c0+q];
                            float K  = Pi / fmaxf(Pi + R, 1e-8f);
                            float dz = z[i][h*4+q] - thv[q];
                            float nu = atan2f(sinf(dz), cosf(dz));
                            Ra[q] = R; Ka[q] = K; Ua[q] = K * nu;
                        }
                        *(float4*)&outR[base] = make_float4(Ra[0], Ra[1], Ra[2], Ra[3]);
                        *(float4*)&outK[base] = make_float4(Ka[0], Ka[1], Ka[2], Ka[3]);
                        *(float4*)&g_u[base]  = make_float4(Ua[0], Ua[1], Ua[2], Ua[3]);
                    }
                }
            }
        }
    }
}

// ---------------------------------------------------------------------------
// Scan: d[t] = alpha[t]*d[t-1] + u[t], alpha = 1-K. Chunked 3-phase scan.
// ---------------------------------------------------------------------------
__global__ void scan_chunks_kernel(const float* __restrict__ Kp) {
    int g = blockIdx.x * blockDim.x + threadIdx.x;   // < kNSEQ*kCH = 262144
    int c = g & (kNS - 1);
    int q = g >> 10;
    int b = q & (kB - 1);
    int chunk = q >> 2;
    size_t base = ((size_t)b * kL + (size_t)chunk * kT) * kNS + c;
    float a = 1.0f, v = 0.0f;
#pragma unroll 4
    for (int t = 0; t < kT; ++t) {
        float K  = Kp[base];
        float u  = g_u[base];
        float al = 1.0f - K;
        v = fmaf(al, v, u);
        a *= al;
        base += kNS;
    }
    int seq = b * kNS + c;
    g_Ag[chunk * kNSEQ + seq] = a;
    g_Vg[chunk * kNSEQ + seq] = v;
}

__global__ void scan_agg_kernel() {
    int seq = blockIdx.x * blockDim.x + threadIdx.x;  // < 4096
    float carry = 0.0f;
    for (int j = 0; j < kCH; ++j) {
        g_cr[j * kNSEQ + seq] = carry;                // exclusive prefix
        carry = fmaf(g_Ag[j * kNSEQ + seq], carry, g_Vg[j * kNSEQ + seq]);
    }
}

__global__ void scan_apply_kernel(const float* __restrict__ Kp,
                                  const float* __restrict__ theta,
                                  float* __restrict__ outTheta) {
    int g = blockIdx.x * blockDim.x + threadIdx.x;
    int c = g & (kNS - 1);
    int q = g >> 10;
    int b = q & (kB - 1);
    int chunk = q >> 2;
    int seq = b * kNS + c;
    float d = g_cr[chunk * kNSEQ + seq];
    size_t base = ((size_t)b * kL + (size_t)chunk * kT) * kNS + c;
#pragma unroll 4
    for (int t = 0; t < kT; ++t) {
        float K = Kp[base];
        float u = g_u[base];
        d = fmaf(1.0f - K, d, u);
        outTheta[base] = theta[base] + d;
        base += kNS;
    }
}

__global__ void pi_kernel(const float* __restrict__ logPi, float* __restrict__ outPi) {
    int i = blockIdx.x * blockDim.x + threadIdx.x;
    if (i < kNS) outPi[i] = expf(logPi[i]);
}

// ---------------------------------------------------------------------------
extern "C" void kernel_launch(void* const* d_in, const int* in_sizes, int n_in,
                              void* d_out, int out_size) {
    const float* theta = (const float*)d_in[0];
    const float* x     = (const float*)d_in[1];
    const float* logPi = (const float*)d_in[2];
    const float* Wr1   = (const float*)d_in[3];
    const float* br1   = (const float*)d_in[4];
    const float* Wr2   = (const float*)d_in[5];
    const float* br2   = (const float*)d_in[6];
    const float* Wm1   = (const float*)d_in[7];
    const float* bm1   = (const float*)d_in[8];
    const float* Wm2   = (const float*)d_in[9];
    const float* bm2   = (const float*)d_in[10];

    float* out      = (float*)d_out;
    float* outTheta = out;                                  // (B,L,H,NB)
    float* outPi    = outTheta + (size_t)kNTOK * kNS;       // (H,NB)
    float* outK     = outPi + kNS;                          // (B,L,H,NB)
    float* outR     = outK + (size_t)kNTOK * kNS;           // (B,L,H,NB)

    const int smem = SMEM_FLOATS * (int)sizeof(float);      // ~108 KB
    cudaFuncSetAttribute(mlp_fused_kernel,
                         cudaFuncAttributeMaxDynamicSharedMemorySize, smem);

    mlp_fused_kernel<<<kNTOK / BM, 256, smem>>>(theta, x, logPi,
                                                Wr1, br1, Wr2, br2,
                                                Wm1, bm1, Wm2, bm2,
                                                outK, outR);
    pi_kernel<<<4, 256>>>(logPi, outPi);
    scan_chunks_kernel<<<(kNSEQ * kCH) / 256, 256>>>(outK);
    scan_agg_kernel<<<kNSEQ / 256, 256>>>();
    scan_apply_kernel<<<(kNSEQ * kCH) / 256, 256>>>(outK, theta, outTheta);
}